// round 12
// baseline (speedup 1.0000x reference)
#include <cuda_runtime.h>

// Malvar-He-Cutler demosaic, GB300 (sm_103a). Round 12:
// R11 compute (own-col aligned LDG.128 + shuffle halos), but outputs go
// smem -> global via cp.async.bulk (bulk_group). Store wavefronts per warp
// drop 72 -> 24 (conflict-free STS.128); the 3KB/row bulk copies ride the
// TMA path instead of L1 STG wavefronts.
// CTA = 256px x 16 rows, block(64,8)=512 threads, 48KB smem out-tile.

__device__ __forceinline__ float clip01(float v) {
    return fminf(fmaxf(v, 0.0f), 1.0f);
}
__device__ __forceinline__ int refl(int i, int n) {
    i = (i < 0) ? -i : i;
    return (i >= n) ? (2 * n - 2 - i) : i;
}
__device__ __forceinline__ unsigned smem_u32(const void* p) {
    return (unsigned)__cvta_generic_to_shared(p);
}

#define OUT_ROW_FLOATS 768   // 256 px * 3 ch
#define OUT_ROW_BYTES  3072

__global__ void __launch_bounds__(512, 2)
demosaic_kernel(const float* __restrict__ x, float* __restrict__ out,
                int H, int W)
{
    __shared__ __align__(16) float s_out[16 * OUT_ROW_FLOATS];  // 48 KB

    const unsigned FM = 0xffffffffu;
    const int tx   = threadIdx.x;                   // 0..63
    const int ty   = threadIdx.y;                   // 0..7
    const int lane = tx & 31;
    const int base_c = (blockIdx.x * 64 + tx) * 4;  // own cols base_c..base_c+3
    const int gr0    = (blockIdx.y * 8 + ty) * 2;   // output rows gr0, gr0+1

    // Reflected row indices for the 6-row window (always valid).
    int rows[6];
    #pragma unroll
    for (int j = 0; j < 6; ++j) rows[j] = refl(gr0 - 2 + j, H);

    const int bc_ld = (base_c + 4 <= W) ? base_c : (W - 4);

    // ---- own 4-col loads: 6 aligned LDG.128 ----
    float4 rv[6];
    #pragma unroll
    for (int j = 0; j < 6; ++j)
        rv[j] = *reinterpret_cast<const float4*>(x + (size_t)rows[j] * W + bc_ld);

    // ---- warp-edge halo loads (2 cols x 6 rows) ----
    const bool is_l = (lane == 0), is_r = (lane == 31);
    float2 hv[6];
    if (is_l | is_r) {
        const int hcol = is_l ? (base_c - 2) : (base_c + 4);
        if (hcol >= 0 && hcol + 2 <= W) {
            #pragma unroll
            for (int j = 0; j < 6; ++j)
                hv[j] = *reinterpret_cast<const float2*>(x + (size_t)rows[j] * W + hcol);
        } else {
            const int h0 = refl(hcol, W), h1 = refl(hcol + 1, W);
            #pragma unroll
            for (int j = 0; j < 6; ++j) {
                hv[j].x = x[(size_t)rows[j] * W + h0];
                hv[j].y = x[(size_t)rows[j] * W + h1];
            }
        }
    }

    // ---- vertical bases over own 4 cols ----
    float ae[4], be[4], ce[4], ao[4], bo[4], co[4];
    {
        float r[6][4];
        #pragma unroll
        for (int j = 0; j < 6; ++j) {
            r[j][0] = rv[j].x; r[j][1] = rv[j].y; r[j][2] = rv[j].z; r[j][3] = rv[j].w;
        }
        #pragma unroll
        for (int i = 0; i < 4; ++i) {
            ae[i] = r[0][i] + r[4][i];
            be[i] = r[1][i] + r[3][i];
            ce[i] = r[2][i];
            ao[i] = r[1][i] + r[5][i];
            bo[i] = r[2][i] + r[4][i];
            co[i] = r[3][i];
        }
    }

    float hce0 = 0, hce1 = 0, hbe0 = 0, hbe1 = 0, hco0 = 0, hco1 = 0, hbo0 = 0, hbo1 = 0;
    if (is_l | is_r) {
        hce0 = hv[2].x;            hce1 = hv[2].y;
        hbe0 = hv[1].x + hv[3].x;  hbe1 = hv[1].y + hv[3].y;
        hco0 = hv[3].x;            hco1 = hv[3].y;
        hbo0 = hv[2].x + hv[4].x;  hbo1 = hv[2].y + hv[4].y;
    }

    // ---- halo bases via shuffle (within warp) ----
    float le_c0 = __shfl_up_sync(FM, ce[2], 1);
    float le_c1 = __shfl_up_sync(FM, ce[3], 1);
    float le_b  = __shfl_up_sync(FM, be[3], 1);
    float lo_c0 = __shfl_up_sync(FM, co[2], 1);
    float lo_c1 = __shfl_up_sync(FM, co[3], 1);
    float lo_b  = __shfl_up_sync(FM, bo[3], 1);
    float re_c0 = __shfl_down_sync(FM, ce[0], 1);
    float re_c1 = __shfl_down_sync(FM, ce[1], 1);
    float re_b  = __shfl_down_sync(FM, be[0], 1);
    float ro_c0 = __shfl_down_sync(FM, co[0], 1);
    float ro_c1 = __shfl_down_sync(FM, co[1], 1);
    float ro_b  = __shfl_down_sync(FM, bo[0], 1);
    if (is_l) { le_c0 = hce0; le_c1 = hce1; le_b = hbe1;
                lo_c0 = hco0; lo_c1 = hco1; lo_b = hbo1; }
    if (is_r) { re_c0 = hce0; re_c1 = hce1; re_b = hbe0;
                ro_c0 = hco0; ro_c1 = hco1; ro_b = hbo0; }

    // ---- compute + STS (conflict-free 48B-stride STS.128) ----
    float* so0 = s_out + (2 * ty)     * OUT_ROW_FLOATS + tx * 12;
    float* so1 = s_out + (2 * ty + 1) * OUT_ROW_FLOATS + tx * 12;

    // Row 0 (even global row): R Gr R Gr
    {
        const float cx[8] = {le_c0, le_c1, ce[0], ce[1], ce[2], ce[3], re_c0, re_c1};
        const float bx[6] = {le_b,  be[0], be[1], be[2], be[3], re_b};
        float o[12];
        #pragma unroll
        for (int p = 0; p < 4; ++p) {
            const float cc = cx[p+2], bb = bx[p+1], aa = ae[p];
            const float s1 = cx[p+1] + cx[p+3];
            const float s2 = cx[p]   + cx[p+4];
            const float s3 = bx[p]   + bx[p+2];
            const float gi  = 0.125f * (4.0f*cc + 2.0f*(bb + s1) - (aa + s2));
            const float rgr = 0.125f * (5.0f*cc + 4.0f*s1 - s2 + 0.5f*aa - s3);
            const float rgv = 0.125f * (5.0f*cc + 4.0f*bb - aa + 0.5f*s2 - s3);
            const float rb  = 0.125f * (6.0f*cc + 2.0f*s3 - 1.5f*(aa + s2));
            if ((p & 1) == 0) { o[3*p]=clip01(cc);  o[3*p+1]=clip01(gi); o[3*p+2]=clip01(rb);  }
            else              { o[3*p]=clip01(rgr); o[3*p+1]=clip01(cc); o[3*p+2]=clip01(rgv); }
        }
        float4* s4 = reinterpret_cast<float4*>(so0);
        s4[0] = make_float4(o[0], o[1], o[2],  o[3]);
        s4[1] = make_float4(o[4], o[5], o[6],  o[7]);
        s4[2] = make_float4(o[8], o[9], o[10], o[11]);
    }

    // Row 1 (odd global row): Gb B Gb B
    {
        const float cx[8] = {lo_c0, lo_c1, co[0], co[1], co[2], co[3], ro_c0, ro_c1};
        const float bx[6] = {lo_b,  bo[0], bo[1], bo[2], bo[3], ro_b};
        float o[12];
        #pragma unroll
        for (int p = 0; p < 4; ++p) {
            const float cc = cx[p+2], bb = bx[p+1], aa = ao[p];
            const float s1 = cx[p+1] + cx[p+3];
            const float s2 = cx[p]   + cx[p+4];
            const float s3 = bx[p]   + bx[p+2];
            const float gi  = 0.125f * (4.0f*cc + 2.0f*(bb + s1) - (aa + s2));
            const float rgr = 0.125f * (5.0f*cc + 4.0f*s1 - s2 + 0.5f*aa - s3);
            const float rgv = 0.125f * (5.0f*cc + 4.0f*bb - aa + 0.5f*s2 - s3);
            const float rb  = 0.125f * (6.0f*cc + 2.0f*s3 - 1.5f*(aa + s2));
            if ((p & 1) == 0) { o[3*p]=clip01(rgv); o[3*p+1]=clip01(cc); o[3*p+2]=clip01(rgr); }
            else              { o[3*p]=clip01(rb);  o[3*p+1]=clip01(gi); o[3*p+2]=clip01(cc);  }
        }
        float4* s4 = reinterpret_cast<float4*>(so1);
        s4[0] = make_float4(o[0], o[1], o[2],  o[3]);
        s4[1] = make_float4(o[4], o[5], o[6],  o[7]);
        s4[2] = make_float4(o[8], o[9], o[10], o[11]);
    }

    __syncthreads();

    // ---- bulk-async smem -> global, one 3072B copy per tile row ----
    const int tid = ty * 64 + tx;
    if (tid < 16) {
        asm volatile("fence.proxy.async.shared::cta;" ::: "memory");
        const int gr = blockIdx.y * 16 + tid;
        if (gr < H) {
            float* dst = out + ((size_t)gr * W + (size_t)blockIdx.x * 256) * 3;
            const unsigned src = smem_u32(s_out + tid * OUT_ROW_FLOATS);
            asm volatile(
                "cp.async.bulk.global.shared::cta.bulk_group [%0], [%1], %2;"
                :: "l"(dst), "r"(src), "r"((unsigned)OUT_ROW_BYTES) : "memory");
            asm volatile("cp.async.bulk.commit_group;" ::: "memory");
            asm volatile("cp.async.bulk.wait_group.read 0;" ::: "memory");
        }
    }
}

extern "C" void kernel_launch(void* const* d_in, const int* in_sizes, int n_in,
                              void* d_out, int out_size)
{
    const float* x = (const float*)d_in[0];
    long nx = in_sizes[0];
    if (n_in > 1 && in_sizes[1] > in_sizes[0]) {  // defensive: pick the big tensor as x
        x = (const float*)d_in[1];
        nx = in_sizes[1];
    }

    const int W = 6144;
    const int H = (int)(nx / W);

    dim3 block(64, 8);                          // 256 px x 16 rows per CTA
    dim3 grid((unsigned)((W + 255) / 256),
              (unsigned)((H + 15) / 16));

    demosaic_kernel<<<grid, block>>>(x, (float*)d_out, H, W);
}

// round 13
// speedup vs baseline: 1.2646x; 1.2646x over previous
#include <cuda_runtime.h>

// Malvar-He-Cutler demosaic, GB300 (sm_103a). Round 13:
// R11 compute (own-col aligned LDG.128 + shuffle halos) + R12 TMA stores,
// but fully WARP-LOCAL: each warp stages its 128px x 2row strip in a private
// 3KB smem slab (conflict-free STS.128), __syncwarp only, lane 0 ships two
// 1536B cp.async.bulk copies. No __syncthreads -> no convoy, stores off L1.

__device__ __forceinline__ float clip01(float v) {
    return fminf(fmaxf(v, 0.0f), 1.0f);
}
__device__ __forceinline__ int refl(int i, int n) {
    i = (i < 0) ? -i : i;
    return (i >= n) ? (2 * n - 2 - i) : i;
}
__device__ __forceinline__ unsigned smem_u32(const void* p) {
    return (unsigned)__cvta_generic_to_shared(p);
}

#define ROW_FLOATS 384       // 128 px * 3 ch
#define ROW_BYTES  1536

__global__ void __launch_bounds__(256, 4)
demosaic_kernel(const float* __restrict__ x, float* __restrict__ out,
                int H, int W)
{
    __shared__ __align__(16) float s_out[8][2][ROW_FLOATS];   // 24 KB, per-warp slabs

    const unsigned FM = 0xffffffffu;
    const int lane = threadIdx.x;                   // 0..31
    const int ty   = threadIdx.y;                   // 0..7 (= warp id)
    const int warp_c0 = blockIdx.x * 128;           // warp's first output col
    const int base_c  = warp_c0 + lane * 4;         // own cols base_c..base_c+3
    const int gr0     = (blockIdx.y * 8 + ty) * 2;  // output rows gr0, gr0+1

    // Reflected row indices for the 6-row window (always valid).
    int rows[6];
    #pragma unroll
    for (int j = 0; j < 6; ++j) rows[j] = refl(gr0 - 2 + j, H);

    const int bc_ld = (base_c + 4 <= W) ? base_c : (W - 4);

    // ---- own 4-col loads: 6 aligned LDG.128 ----
    float4 rv[6];
    #pragma unroll
    for (int j = 0; j < 6; ++j)
        rv[j] = *reinterpret_cast<const float4*>(x + (size_t)rows[j] * W + bc_ld);

    // ---- warp-edge halo loads (2 cols x 6 rows) ----
    const bool is_l = (lane == 0), is_r = (lane == 31);
    float2 hv[6];
    if (is_l | is_r) {
        const int hcol = is_l ? (base_c - 2) : (base_c + 4);
        if (hcol >= 0 && hcol + 2 <= W) {
            #pragma unroll
            for (int j = 0; j < 6; ++j)
                hv[j] = *reinterpret_cast<const float2*>(x + (size_t)rows[j] * W + hcol);
        } else {
            const int h0 = refl(hcol, W), h1 = refl(hcol + 1, W);
            #pragma unroll
            for (int j = 0; j < 6; ++j) {
                hv[j].x = x[(size_t)rows[j] * W + h0];
                hv[j].y = x[(size_t)rows[j] * W + h1];
            }
        }
    }

    // ---- vertical bases over own 4 cols ----
    float ae[4], be[4], ce[4], ao[4], bo[4], co[4];
    {
        float r[6][4];
        #pragma unroll
        for (int j = 0; j < 6; ++j) {
            r[j][0] = rv[j].x; r[j][1] = rv[j].y; r[j][2] = rv[j].z; r[j][3] = rv[j].w;
        }
        #pragma unroll
        for (int i = 0; i < 4; ++i) {
            ae[i] = r[0][i] + r[4][i];
            be[i] = r[1][i] + r[3][i];
            ce[i] = r[2][i];
            ao[i] = r[1][i] + r[5][i];
            bo[i] = r[2][i] + r[4][i];
            co[i] = r[3][i];
        }
    }

    float hce0 = 0, hce1 = 0, hbe0 = 0, hbe1 = 0, hco0 = 0, hco1 = 0, hbo0 = 0, hbo1 = 0;
    if (is_l | is_r) {
        hce0 = hv[2].x;            hce1 = hv[2].y;
        hbe0 = hv[1].x + hv[3].x;  hbe1 = hv[1].y + hv[3].y;
        hco0 = hv[3].x;            hco1 = hv[3].y;
        hbo0 = hv[2].x + hv[4].x;  hbo1 = hv[2].y + hv[4].y;
    }

    // ---- halo bases via shuffle ----
    float le_c0 = __shfl_up_sync(FM, ce[2], 1);
    float le_c1 = __shfl_up_sync(FM, ce[3], 1);
    float le_b  = __shfl_up_sync(FM, be[3], 1);
    float lo_c0 = __shfl_up_sync(FM, co[2], 1);
    float lo_c1 = __shfl_up_sync(FM, co[3], 1);
    float lo_b  = __shfl_up_sync(FM, bo[3], 1);
    float re_c0 = __shfl_down_sync(FM, ce[0], 1);
    float re_c1 = __shfl_down_sync(FM, ce[1], 1);
    float re_b  = __shfl_down_sync(FM, be[0], 1);
    float ro_c0 = __shfl_down_sync(FM, co[0], 1);
    float ro_c1 = __shfl_down_sync(FM, co[1], 1);
    float ro_b  = __shfl_down_sync(FM, bo[0], 1);
    if (is_l) { le_c0 = hce0; le_c1 = hce1; le_b = hbe1;
                lo_c0 = hco0; lo_c1 = hco1; lo_b = hbo1; }
    if (is_r) { re_c0 = hce0; re_c1 = hce1; re_b = hbe0;
                ro_c0 = hco0; ro_c1 = hco1; ro_b = hbo0; }

    // ---- compute + per-warp STS (48B lane stride, conflict-free phases) ----
    float4* s0 = reinterpret_cast<float4*>(&s_out[ty][0][lane * 12]);
    float4* s1 = reinterpret_cast<float4*>(&s_out[ty][1][lane * 12]);

    // Row 0 (even global row): R Gr R Gr
    {
        const float cx[8] = {le_c0, le_c1, ce[0], ce[1], ce[2], ce[3], re_c0, re_c1};
        const float bx[6] = {le_b,  be[0], be[1], be[2], be[3], re_b};
        float o[12];
        #pragma unroll
        for (int p = 0; p < 4; ++p) {
            const float cc = cx[p+2], bb = bx[p+1], aa = ae[p];
            const float s1v = cx[p+1] + cx[p+3];
            const float s2v = cx[p]   + cx[p+4];
            const float s3v = bx[p]   + bx[p+2];
            const float gi  = 0.125f * (4.0f*cc + 2.0f*(bb + s1v) - (aa + s2v));
            const float rgr = 0.125f * (5.0f*cc + 4.0f*s1v - s2v + 0.5f*aa - s3v);
            const float rgv = 0.125f * (5.0f*cc + 4.0f*bb - aa + 0.5f*s2v - s3v);
            const float rb  = 0.125f * (6.0f*cc + 2.0f*s3v - 1.5f*(aa + s2v));
            if ((p & 1) == 0) { o[3*p]=clip01(cc);  o[3*p+1]=clip01(gi); o[3*p+2]=clip01(rb);  }
            else              { o[3*p]=clip01(rgr); o[3*p+1]=clip01(cc); o[3*p+2]=clip01(rgv); }
        }
        s0[0] = make_float4(o[0], o[1], o[2],  o[3]);
        s0[1] = make_float4(o[4], o[5], o[6],  o[7]);
        s0[2] = make_float4(o[8], o[9], o[10], o[11]);
    }

    // Row 1 (odd global row): Gb B Gb B
    {
        const float cx[8] = {lo_c0, lo_c1, co[0], co[1], co[2], co[3], ro_c0, ro_c1};
        const float bx[6] = {lo_b,  bo[0], bo[1], bo[2], bo[3], ro_b};
        float o[12];
        #pragma unroll
        for (int p = 0; p < 4; ++p) {
            const float cc = cx[p+2], bb = bx[p+1], aa = ao[p];
            const float s1v = cx[p+1] + cx[p+3];
            const float s2v = cx[p]   + cx[p+4];
            const float s3v = bx[p]   + bx[p+2];
            const float gi  = 0.125f * (4.0f*cc + 2.0f*(bb + s1v) - (aa + s2v));
            const float rgr = 0.125f * (5.0f*cc + 4.0f*s1v - s2v + 0.5f*aa - s3v);
            const float rgv = 0.125f * (5.0f*cc + 4.0f*bb - aa + 0.5f*s2v - s3v);
            const float rb  = 0.125f * (6.0f*cc + 2.0f*s3v - 1.5f*(aa + s2v));
            if ((p & 1) == 0) { o[3*p]=clip01(rgv); o[3*p+1]=clip01(cc); o[3*p+2]=clip01(rgr); }
            else              { o[3*p]=clip01(rb);  o[3*p+1]=clip01(gi); o[3*p+2]=clip01(cc);  }
        }
        s1[0] = make_float4(o[0], o[1], o[2],  o[3]);
        s1[1] = make_float4(o[4], o[5], o[6],  o[7]);
        s1[2] = make_float4(o[8], o[9], o[10], o[11]);
    }

    __syncwarp();

    const bool full = (warp_c0 + 128 <= W) && (gr0 + 2 <= H);
    if (full) {
        if (lane == 0) {
            asm volatile("fence.proxy.async.shared::cta;" ::: "memory");
            float* dst0 = out + ((size_t)gr0 * W + warp_c0) * 3;
            float* dst1 = out + ((size_t)(gr0 + 1) * W + warp_c0) * 3;
            const unsigned src0 = smem_u32(&s_out[ty][0][0]);
            const unsigned src1 = smem_u32(&s_out[ty][1][0]);
            asm volatile("cp.async.bulk.global.shared::cta.bulk_group [%0], [%1], %2;"
                         :: "l"(dst0), "r"(src0), "r"((unsigned)ROW_BYTES) : "memory");
            asm volatile("cp.async.bulk.global.shared::cta.bulk_group [%0], [%1], %2;"
                         :: "l"(dst1), "r"(src1), "r"((unsigned)ROW_BYTES) : "memory");
            asm volatile("cp.async.bulk.commit_group;" ::: "memory");
            asm volatile("cp.async.bulk.wait_group 0;" ::: "memory");
        }
    } else {
        // ragged edge: direct scalar stores from smem values this lane wrote
        #pragma unroll
        for (int rr = 0; rr < 2; ++rr) {
            const int gr = gr0 + rr;
            if (gr >= H) break;
            #pragma unroll
            for (int p = 0; p < 4; ++p) {
                const int col = base_c + p;
                if (col < W) {
                    float* q2 = out + ((size_t)gr * W + col) * 3;
                    q2[0] = s_out[ty][rr][lane * 12 + 3 * p];
                    q2[1] = s_out[ty][rr][lane * 12 + 3 * p + 1];
                    q2[2] = s_out[ty][rr][lane * 12 + 3 * p + 2];
                }
            }
        }
    }
}

extern "C" void kernel_launch(void* const* d_in, const int* in_sizes, int n_in,
                              void* d_out, int out_size)
{
    const float* x = (const float*)d_in[0];
    long nx = in_sizes[0];
    if (n_in > 1 && in_sizes[1] > in_sizes[0]) {  // defensive: pick the big tensor as x
        x = (const float*)d_in[1];
        nx = in_sizes[1];
    }

    const int W = 6144;
    const int H = (int)(nx / W);

    dim3 block(32, 8);                          // 128 px x 16 rows per CTA
    dim3 grid((unsigned)((W + 127) / 128),
              (unsigned)((H + 15) / 16));

    demosaic_kernel<<<grid, block>>>(x, (float*)d_out, H, W);
}